// round 13
// baseline (speedup 1.0000x reference)
#include <cuda_runtime.h>
#include <cuda_fp16.h>
#include <cstdint>

#define BB 32
#define NN 2048
#define CIN 64
#define COUTC 128
#define ADJ_EPS 1e-6f
#define BN_EPS 1e-5f

// smem geometry
#define XH_STRIDE 20                        // xh row stride (words); (20ar+ac)%32 all distinct
#define XH_STAGE (64 * XH_STRIDE * 4)       // 5120 B per stage, 3 stages
#define AF_STRIDE 136                       // A fp32 row stride (words); (8ac+ar)%32 distinct
#define AF_STAGE (32 * AF_STRIDE * 4)       // 17408 B per stage, 3 stages
#define AF_BASE (3 * XH_STAGE)              // 15360
#define SMEM_BYTES (AF_BASE + 3 * AF_STAGE) // 67584; 3 CTAs = 202752 <= SM smem
                                            // epilogue needs 34816 floats-bytes, fits

// ---------------- scratch (device globals; no allocations allowed) ----------
__device__ float g_invS[BB * NN];
__device__ uint32_t g_xh[(size_t)BB * 64 * 1024]; // half2{xs[c][32g+j], xs[c][32g+j+16]}
__device__ float g_h[(size_t)BB * NN * COUTC];    // pre-BN activations [b][m][o]
__device__ float g_stats[2 * COUTC];

__device__ __forceinline__ uint32_t smem_u32(const void* p) {
    uint32_t a;
    asm("{ .reg .u64 t; cvta.to.shared.u64 t, %1; cvt.u32.u64 %0, t; }" : "=r"(a) : "l"(p));
    return a;
}
__device__ __forceinline__ void cp16(uint32_t dst, const void* src) {
    asm volatile("cp.async.cg.shared.global [%0], [%1], 16;" :: "r"(dst), "l"(src));
}
__device__ __forceinline__ uint32_t pack2(float lo, float hi) {
    __half2 h = __floats2half2_rn(lo, hi);
    return *reinterpret_cast<uint32_t*>(&h);
}

// ---------------------------------------------------------------------------
// K0: zero g_stats (also keeps the ncu capture slot on k_gemm).
// ---------------------------------------------------------------------------
__global__ void k_zero() {
    if (threadIdx.x < 2 * COUTC) g_stats[threadIdx.x] = 0.f;
}

// ---------------------------------------------------------------------------
// K1: row sums of A (one warp per row).
// ---------------------------------------------------------------------------
__global__ void k_rowsum(const float* __restrict__ A) {
    int row = blockIdx.x * (blockDim.x >> 5) + (threadIdx.x >> 5);
    int lane = threadIdx.x & 31;
    if (row >= BB * NN) return;
    const float4* Ar = reinterpret_cast<const float4*>(A + (size_t)row * NN);
    float s = 0.f;
#pragma unroll 4
    for (int i = lane; i < NN / 4; i += 32) {
        float4 v = Ar[i];
        s += v.x + v.y + v.z + v.w;
    }
#pragma unroll
    for (int o = 16; o; o >>= 1) s += __shfl_xor_sync(0xFFFFFFFFu, s, o);
    if (lane == 0) g_invS[row] = 1.0f / (s + ADJ_EPS);
}

// ---------------------------------------------------------------------------
// K1b: paired fp16 xsT: g_xh[b][c][g*16+j] = half2{xs(32g+j), xs(32g+j+16)}
// ---------------------------------------------------------------------------
__global__ void __launch_bounds__(256) k_prep(const float* __restrict__ x) {
    __shared__ float sx[64 * 65];
    __shared__ float sinv[64];
    const int b = blockIdx.y, n0 = blockIdx.x * 64, tid = threadIdx.x;
    if (tid < 64) sinv[tid] = g_invS[b * NN + n0 + tid];
#pragma unroll
    for (int l = 0; l < 4; l++) {
        int i = tid + 256 * l;
        int n = i >> 4, c4 = i & 15;
        float4 v = *reinterpret_cast<const float4*>(x + ((size_t)b * NN + n0 + n) * 64 + c4 * 4);
        sx[n * 65 + c4 * 4 + 0] = v.x;
        sx[n * 65 + c4 * 4 + 1] = v.y;
        sx[n * 65 + c4 * 4 + 2] = v.z;
        sx[n * 65 + c4 * 4 + 3] = v.w;
    }
    __syncthreads();
#pragma unroll
    for (int l = 0; l < 8; l++) {
        int i = tid + 256 * l;
        int c = i >> 5, q = i & 31;
        int half = q >> 4, j = q & 15;
        int nl = half * 32 + j, nh = nl + 16;
        g_xh[(size_t)(b * 64 + c) * 1024 + (n0 / 32 + half) * 16 + j] =
            pack2(sx[nl * 65 + c] * sinv[nl], sx[nh * 65 + c] * sinv[nh]);
    }
}

// ---------------------------------------------------------------------------
// K2: fp16 m16n8k16 mma GEMM. A arrives fp32 via cp.async ring; fp16
// conversion happens at b-fragment build (LDS fp32 x2 + F2FP pack).
// Per CTA: D[c(64), m(128)] = sum_n xh[c][n] * A[n][m0+m]*invS[n], K = 2048.
// 64 chunks of 32 k; warps: wc(2, c-half) x wm(4, m-group of 32).
// ---------------------------------------------------------------------------
__global__ void __launch_bounds__(256, 3) k_gemm(const float* __restrict__ A,
                                                 const float* __restrict__ Wm,
                                                 const float* __restrict__ bias) {
    extern __shared__ float sm[];
    __shared__ float s_sum[COUTC], s_sq[COUTC];

    char* smc = reinterpret_cast<char*>(sm);
    const uint32_t smb = smem_u32(sm);
    const int tid = threadIdx.x;
    const int w = tid >> 5, lane = tid & 31;
    const int wc = w & 1, wm = w >> 1;
    const int bb = blockIdx.y, m0 = blockIdx.x * 128;
    const float* Ab = A + (size_t)bb * NN * NN;
    const uint32_t* xhb = g_xh + (size_t)bb * 64 * 1024;

    float acc[2][4][4];
#pragma unroll
    for (int mt = 0; mt < 2; mt++)
#pragma unroll
        for (int nt = 0; nt < 4; nt++)
#pragma unroll
            for (int j = 0; j < 4; j++) acc[mt][nt][j] = 0.f;

    const int lx_c = tid >> 2, lx_q = tid & 3;   // xh: 64 rows x 4x16B
    const int la_r = tid >> 3, la_q = tid & 7;   // A:  32 rows x 8x16B x4 cols

#define ISSUE(ch) do {                                                        \
    uint32_t xd = smb + ((ch) % 3) * XH_STAGE + lx_c * (XH_STRIDE * 4);       \
    cp16(xd + lx_q * 16, xhb + (size_t)lx_c * 1024 + (ch) * 16 + lx_q * 4);   \
    uint32_t ad = smb + AF_BASE + ((ch) % 3) * AF_STAGE                       \
                  + la_r * (AF_STRIDE * 4) + la_q * 16;                       \
    const float* as = Ab + (size_t)((ch) * 32 + la_r) * NN + m0 + la_q * 4;   \
    cp16(ad, as);                                                             \
    cp16(ad + 128, as + 32);                                                  \
    cp16(ad + 256, as + 64);                                                  \
    cp16(ad + 384, as + 96);                                                  \
} while (0)

    ISSUE(0);
    asm volatile("cp.async.commit_group;");
    ISSUE(1);
    asm volatile("cp.async.commit_group;");

    const int ar = lane >> 2, ac = lane & 3;

    for (int ch = 0; ch < 64; ch++) {
        asm volatile("cp.async.wait_group 1;");
        __syncthreads();

        if (ch + 2 < 64) ISSUE(ch + 2);   // stage (ch-1)%3: all readers passed this sync
        asm volatile("cp.async.commit_group;");

        const uint32_t* sX = reinterpret_cast<const uint32_t*>(smc + (ch % 3) * XH_STAGE);
        const float* sF = reinterpret_cast<const float*>(smc + AF_BASE + (ch % 3) * AF_STAGE);

#pragma unroll
        for (int ks = 0; ks < 2; ks++) {
            const int koff = ks * 8;
            uint32_t a[2][4];
#pragma unroll
            for (int mt = 0; mt < 2; mt++) {
                const uint32_t* b0 = sX + (wc * 32 + mt * 16 + ar) * XH_STRIDE + koff + ac;
                const uint32_t* b1 = b0 + 8 * XH_STRIDE;
                a[mt][0] = b0[0];
                a[mt][1] = b1[0];
                a[mt][2] = b0[4];
                a[mt][3] = b1[4];
            }
            uint32_t b[4][2];
#pragma unroll
            for (int nt = 0; nt < 4; nt++) {
                const float* p0 = sF + (koff + ac) * AF_STRIDE + wm * 32 + nt * 8 + ar;
                b[nt][0] = pack2(p0[0], p0[16 * AF_STRIDE]);
                b[nt][1] = pack2(p0[4 * AF_STRIDE], p0[20 * AF_STRIDE]);
            }
#pragma unroll
            for (int mt = 0; mt < 2; mt++)
#pragma unroll
                for (int nt = 0; nt < 4; nt++)
                    asm volatile(
                        "mma.sync.aligned.m16n8k16.row.col.f32.f16.f16.f32 "
                        "{%0,%1,%2,%3}, {%4,%5,%6,%7}, {%8,%9}, {%0,%1,%2,%3};"
                        : "+f"(acc[mt][nt][0]), "+f"(acc[mt][nt][1]),
                          "+f"(acc[mt][nt][2]), "+f"(acc[mt][nt][3])
                        : "r"(a[mt][0]), "r"(a[mt][1]), "r"(a[mt][2]), "r"(a[mt][3]),
                          "r"(b[nt][0]), "r"(b[nt][1]));
        }
    }
    __syncthreads();   // all compute done before smem reuse for xg

    // ---- accumulators -> smem xg[m][68 stride] (conflict-free scatter) ----
#pragma unroll
    for (int mt = 0; mt < 2; mt++)
#pragma unroll
        for (int nt = 0; nt < 4; nt++) {
            int cr = wc * 32 + mt * 16 + (lane >> 2);
            int mc = wm * 32 + nt * 8 + 2 * (lane & 3);
            sm[mc * 68 + cr]           = acc[mt][nt][0];
            sm[(mc + 1) * 68 + cr]     = acc[mt][nt][1];
            sm[mc * 68 + cr + 8]       = acc[mt][nt][2];
            sm[(mc + 1) * 68 + cr + 8] = acc[mt][nt][3];
        }
    if (tid < COUTC) { s_sum[tid] = 0.f; s_sq[tid] = 0.f; }
    __syncthreads();

    // ---- epilogue: h = xg @ W^T + bias, BN stats, store h ----
    const float4* W4 = reinterpret_cast<const float4*>(Wm);
    const int tx = tid & 15, ty = tid >> 4;
#pragma unroll
    for (int op = 0; op < 4; op++) {
        int o0 = tx * 8 + op * 2;
        float h0[8], h1[8];
#pragma unroll
        for (int mi = 0; mi < 8; mi++) { h0[mi] = 0.f; h1[mi] = 0.f; }
#pragma unroll
        for (int c4 = 0; c4 < 16; c4++) {
            float4 w0 = W4[(size_t)o0 * 16 + c4];
            float4 w1 = W4[(size_t)(o0 + 1) * 16 + c4];
#pragma unroll
            for (int mi = 0; mi < 8; mi++) {
                float4 g = *reinterpret_cast<const float4*>(&sm[(ty * 8 + mi) * 68 + c4 * 4]);
                h0[mi] += g.x * w0.x + g.y * w0.y + g.z * w0.z + g.w * w0.w;
                h1[mi] += g.x * w1.x + g.y * w1.y + g.z * w1.z + g.w * w1.w;
            }
        }
        float b0 = bias[o0], b1 = bias[o0 + 1];
        float sA2 = 0.f, qA = 0.f, sB2 = 0.f, qB = 0.f;
        size_t base = ((size_t)bb * NN + m0 + ty * 8) * COUTC + o0;
#pragma unroll
        for (int mi = 0; mi < 8; mi++) {
            float v0 = h0[mi] + b0, v1 = h1[mi] + b1;
            sA2 += v0; qA += v0 * v0;
            sB2 += v1; qB += v1 * v1;
            *reinterpret_cast<float2*>(&g_h[base + (size_t)mi * COUTC]) = make_float2(v0, v1);
        }
        atomicAdd(&s_sum[o0], sA2);     atomicAdd(&s_sq[o0], qA);
        atomicAdd(&s_sum[o0 + 1], sB2); atomicAdd(&s_sq[o0 + 1], qB);
    }
    __syncthreads();
    if (tid < COUTC)          atomicAdd(&g_stats[tid], s_sum[tid]);
    else if (tid < 2 * COUTC) atomicAdd(&g_stats[tid], s_sq[tid - COUTC]);
}

// ---------------------------------------------------------------------------
// K3: BN finalize + ReLU (g_h layout == output layout)
// ---------------------------------------------------------------------------
__global__ void k_bn(float* __restrict__ out,
                     const float* __restrict__ gamma,
                     const float* __restrict__ beta) {
    __shared__ float s_scale[COUTC], s_shift[COUTC];
    if (threadIdx.x < COUTC) {
        int o = threadIdx.x;
        float cnt = (float)(BB * NN);
        float mean = g_stats[o] / cnt;
        float var = g_stats[o + COUTC] / cnt - mean * mean;
        float sc = gamma[o] * rsqrtf(var + BN_EPS);
        s_scale[o] = sc;
        s_shift[o] = beta[o] - mean * sc;
    }
    __syncthreads();
    const size_t total = (size_t)BB * NN * COUTC / 4;
    const float4* h4 = reinterpret_cast<const float4*>(g_h);
    float4* o4 = reinterpret_cast<float4*>(out);
    for (size_t idx = (size_t)blockIdx.x * blockDim.x + threadIdx.x; idx < total;
         idx += (size_t)gridDim.x * blockDim.x) {
        float4 v = h4[idx];
        int o = ((int)idx & 31) * 4;
        v.x = fmaxf(fmaf(v.x, s_scale[o + 0], s_shift[o + 0]), 0.f);
        v.y = fmaxf(fmaf(v.y, s_scale[o + 1], s_shift[o + 1]), 0.f);
        v.z = fmaxf(fmaf(v.z, s_scale[o + 2], s_shift[o + 2]), 0.f);
        v.w = fmaxf(fmaf(v.w, s_scale[o + 3], s_shift[o + 3]), 0.f);
        o4[idx] = v;
    }
}

extern "C" void kernel_launch(void* const* d_in, const int* in_sizes, int n_in,
                              void* d_out, int out_size) {
    const float* x     = (const float*)d_in[0];
    const float* A     = (const float*)d_in[1];
    const float* W     = (const float*)d_in[2];
    const float* bias  = (const float*)d_in[3];
    const float* gamma = (const float*)d_in[4];
    const float* beta  = (const float*)d_in[5];
    float* out = (float*)d_out;

    cudaFuncSetAttribute(k_gemm, cudaFuncAttributeMaxDynamicSharedMemorySize, SMEM_BYTES);

    k_zero<<<1, 256>>>();
    k_rowsum<<<BB * NN / 8, 256>>>(A);
    dim3 gp(NN / 64, BB);
    k_prep<<<gp, 256>>>(x);
    dim3 g2(NN / 128, BB);
    k_gemm<<<g2, 256, SMEM_BYTES>>>(A, W, bias);
    k_bn<<<4096, 256>>>(out, gamma, beta);
}